// round 16
// baseline (speedup 1.0000x reference)
#include <cuda_runtime.h>
#include <cuda_fp16.h>
#include <cstdint>

#define SEQ 4096
#define HID 2048
#define NHEADS 16
#define HD 128

// Q pre-scale: (1/sqrt(128)) * log2(e)  -> softmax runs in exp2 domain
#define QSC 0.12751291181090523f

// ---------------- scratch (static device arrays; no allocation) ----------------
static __device__ __half g_Xh[SEQ * HID];
static __device__ __half g_Wqh[HID * HID];
static __device__ __half g_Wkh[HID * HID];
static __device__ __half g_Wvh[HID * HID];
static __device__ __half g_Woh[HID * HID];
static __device__ __half g_Qh[SEQ * HID];
static __device__ __half g_Kh[SEQ * HID];
static __device__ __half g_Vt[HID * SEQ];    // V TRANSPOSED: [dim][seq]
static __device__ __half g_ctxh[SEQ * HID];
static __device__ float  g_cos[SEQ * 64];
static __device__ float  g_sin[SEQ * 64];

// ---------------- helpers ----------------
__device__ __forceinline__ void mma_f16(float* c, const uint32_t* a, uint32_t b0, uint32_t b1) {
    asm volatile(
        "mma.sync.aligned.m16n8k16.row.col.f32.f16.f16.f32 "
        "{%0,%1,%2,%3}, {%4,%5,%6,%7}, {%8,%9}, {%0,%1,%2,%3};"
        : "+f"(c[0]), "+f"(c[1]), "+f"(c[2]), "+f"(c[3])
        : "r"(a[0]), "r"(a[1]), "r"(a[2]), "r"(a[3]), "r"(b0), "r"(b1));
}

__device__ __forceinline__ void ldsm4(uint32_t& r0, uint32_t& r1, uint32_t& r2, uint32_t& r3,
                                      uint32_t addr) {
    asm volatile("ldmatrix.sync.aligned.m8n8.x4.shared.b16 {%0,%1,%2,%3}, [%4];"
                 : "=r"(r0), "=r"(r1), "=r"(r2), "=r"(r3) : "r"(addr));
}

__device__ __forceinline__ void cpasync16(uint32_t dst, const void* src) {
    asm volatile("cp.async.cg.shared.global [%0], [%1], 16;" :: "r"(dst), "l"(src));
}
__device__ __forceinline__ void cpcommit() { asm volatile("cp.async.commit_group;"); }

__device__ __forceinline__ uint32_t h2u(__half2 h) {
    return *reinterpret_cast<uint32_t*>(&h);
}
__device__ __forceinline__ uint32_t ex2_h2(uint32_t x) {
    uint32_t r;
    asm("ex2.approx.f16x2 %0, %1;" : "=r"(r) : "r"(x));
    return r;
}

// ---------------- prep: fp32 -> fp16, 4 float4s per thread (MLP) --------------
#define NX (SEQ * HID / 4)
#define NW (HID * HID / 4)
#define NTOT (NX + 4 * NW)
__global__ void tohalf_all(const float* __restrict__ X,  const float* __restrict__ Wq,
                           const float* __restrict__ Wk, const float* __restrict__ Wv,
                           const float* __restrict__ Wo) {
    int base = blockIdx.x * (blockDim.x * 4) + threadIdx.x;
#pragma unroll
    for (int u = 0; u < 4; u++) {
        int i = base + u * blockDim.x;
        if (i >= NTOT) return;
        const float* src; __half* dst; int off;
        if (i < NX)               { src = X;  dst = g_Xh;  off = i; }
        else if (i < NX + NW)     { src = Wq; dst = g_Wqh; off = i - NX; }
        else if (i < NX + 2 * NW) { src = Wk; dst = g_Wkh; off = i - NX - NW; }
        else if (i < NX + 3 * NW) { src = Wv; dst = g_Wvh; off = i - NX - 2 * NW; }
        else                      { src = Wo; dst = g_Woh; off = i - NX - 3 * NW; }
        float4 v = reinterpret_cast<const float4*>(src)[off];
        __half2* p = reinterpret_cast<__half2*>(&dst[4 * off]);
        p[0] = __floats2half2_rn(v.x, v.y);
        p[1] = __floats2half2_rn(v.z, v.w);
    }
}

// ---------------- RoPE tables ----------------
__global__ void rope_table() {
    int idx = blockIdx.x * blockDim.x + threadIdx.x;
    if (idx >= SEQ * 64) return;
    int s = idx >> 6, j = idx & 63;
    double invf = exp(-(double)j * (9.210340371976184 / 64.0));  // 10000^(-j/64)
    float freq = (float)s * (float)invf;                          // fp32, like the ref
    g_cos[idx] = (float)cos((double)freq);
    g_sin[idx] = (float)sin((double)freq);
}

// ---------------- GEMM: C[M,N] = A[M,K] @ B[N,K]^T, fp16 mma, GBK=64, 3-stage --
// Single barrier per k-iteration: passing the post-wait barrier at iter kt
// proves all warps finished compute kt-1, so the subsequent load may safely
// overwrite the stage compute kt-1 used.
#define GBM 128
#define GBN 128
#define GBK 64
#define GST 3
#define APITCH 72                          // halves
#define AHALFS (GBM * APITCH)              // 9216
#define STGH (2 * AHALFS)                  // 18432 halves = 36864 B
#define GEMM_SMEM (GST * STGH * 2)         // 110592 B  (2 CTAs/SM)
#define CPITCH 132                         // fp32 epilogue staging pitch

__global__ void __launch_bounds__(256, 2) gemm_tn(int mode, float* __restrict__ extC) {
    extern __shared__ __half sm[];
    const __half* A; const __half* B;
    float* Cf = nullptr; __half* Ch = nullptr;
    int N;
    const int K = HID;
    int z = (int)blockIdx.z;
    int bm, bn;
    if (mode == 0) {
        if (z == 0)      { A = g_Xh;  B = g_Wqh; N = HID; }
        else if (z == 1) { A = g_Xh;  B = g_Wkh; N = HID; }
        else             { A = g_Wvh; B = g_Xh;  N = SEQ; Ch = g_Vt; }
        if (z == 2) { bm = blockIdx.x * GBM; bn = blockIdx.y * GBN; }   // 16 x 32
        else        { bm = blockIdx.y * GBM; bn = blockIdx.x * GBN; }   // 32 x 16
    } else {
        A = g_ctxh; B = g_Woh; N = HID; Cf = extC;
        bm = blockIdx.y * GBM; bn = blockIdx.x * GBN;
    }

    int tid = threadIdx.x;
    int lane = tid & 31, wid = tid >> 5;
    int wm = wid & 3, wn = wid >> 2;

    float c[2][8][4];
#pragma unroll
    for (int im = 0; im < 2; im++)
#pragma unroll
        for (int jn = 0; jn < 8; jn++)
#pragma unroll
            for (int q = 0; q < 4; q++) c[im][jn][q] = 0.f;

    const __half* Abase = A + (size_t)bm * K;
    const __half* Bbase = B + (size_t)bn * K;

    uint32_t smb = (uint32_t)__cvta_generic_to_shared(sm);

    int lr = tid >> 3, lc8 = tid & 7;

    // ldmatrix lane address components
    int lrow = lane & 7;
    int arow = ((lane >> 3) & 1) * 8 + lrow;   // A: m0/m1 = row-halves, m2/m3 = k-hi
    int acol = (lane >> 4) * 8;
    int brow = (lane >> 4) * 8 + lrow;         // B: m0/m1 = k-halves of jj, m2/m3 = jj+1
    int bcol = ((lane >> 3) & 1) * 8;

    auto load_tile = [&](int s, int kt) {
        int koff = kt * GBK + lc8 * 8;
        uint32_t sa = smb + (uint32_t)(s * STGH) * 2;
        uint32_t sb = sa + AHALFS * 2;
        uint32_t doff = (uint32_t)(lr * APITCH + lc8 * 8) * 2;
#pragma unroll
        for (int i = 0; i < 4; i++) {
            int r = lr + 32 * i;
            cpasync16(sa + doff + (uint32_t)(32 * i * APITCH) * 2, Abase + (size_t)r * K + koff);
            cpasync16(sb + doff + (uint32_t)(32 * i * APITCH) * 2, Bbase + (size_t)r * K + koff);
        }
    };

    const int NT = K / GBK;  // 32
    load_tile(0, 0); cpcommit();
    load_tile(1, 1); cpcommit();

    int g = lane >> 2, t = lane & 3;
    int stg = 0;

    for (int kt = 0; kt < NT; kt++) {
        if (kt + 2 < NT) {
            asm volatile("cp.async.wait_group 1;" ::: "memory");
            __syncthreads();
            int ns = stg + 2; if (ns >= GST) ns -= GST;
            load_tile(ns, kt + 2);
            cpcommit();
        } else {
            asm volatile("cp.async.wait_group 0;" ::: "memory");
            __syncthreads();
        }

        uint32_t saU = smb + (uint32_t)(stg * STGH) * 2;
        uint32_t sbU = saU + AHALFS * 2;
#pragma unroll
        for (int ks = 0; ks < 4; ks++) {
            int k0 = ks * 16;
            uint32_t a[2][4], b[8][2];
#pragma unroll
            for (int im = 0; im < 2; im++) {
                uint32_t addr = saU +
                    (uint32_t)(((wm * 32 + im * 16 + arow) * APITCH + k0 + acol) * 2);
                ldsm4(a[im][0], a[im][1], a[im][2], a[im][3], addr);
            }
#pragma unroll
            for (int jj = 0; jj < 8; jj += 2) {
                uint32_t addr = sbU +
                    (uint32_t)(((wn * 64 + jj * 8 + brow) * APITCH + k0 + bcol) * 2);
                ldsm4(b[jj][0], b[jj][1], b[jj + 1][0], b[jj + 1][1], addr);
            }
#pragma unroll
            for (int im = 0; im < 2; im++)
#pragma unroll
                for (int jn = 0; jn < 8; jn++)
                    mma_f16(c[im][jn], a[im], b[jn][0], b[jn][1]);
        }
        if (++stg == GST) stg = 0;
    }

    if (mode == 0 && z < 2) {
        // ---- fused RoPE epilogue: stage fp32 C in smem, pair (i, i+64), write half
        __syncthreads();                       // mainloop smem reads done
        float* cs = reinterpret_cast<float*>(sm);
#pragma unroll
        for (int im = 0; im < 2; im++)
#pragma unroll
            for (int jn = 0; jn < 8; jn++) {
                int r = wm * 32 + im * 16 + g;
                int lc = wn * 64 + jn * 8 + 2 * t;
                cs[r * CPITCH + lc]           = c[im][jn][0];
                cs[r * CPITCH + lc + 1]       = c[im][jn][1];
                cs[(r + 8) * CPITCH + lc]     = c[im][jn][2];
                cs[(r + 8) * CPITCH + lc + 1] = c[im][jn][3];
            }
        __syncthreads();
        __half* dst = (z == 0) ? g_Qh : g_Kh;
        float qs = (z == 0) ? QSC : 1.0f;      // Q carries softmax scale (log2 domain)
        int r = tid >> 1;
        int i0 = (tid & 1) * 32;
        int s = bm + r;
        const float* crow = cs + r * CPITCH;
#pragma unroll
        for (int ii = 0; ii < 32; ii += 4) {
            int i = i0 + ii;
            float4 x1 = *reinterpret_cast<const float4*>(&crow[i]);
            float4 x2 = *reinterpret_cast<const float4*>(&crow[i + 64]);
            float4 co = *reinterpret_cast<const float4*>(&g_cos[s * 64 + i]);
            float4 si = *reinterpret_cast<const float4*>(&g_sin[s * 64 + i]);
            __half2* d1 = reinterpret_cast<__half2*>(&dst[(size_t)s * HID + bn + i]);
            __half2* d2 = reinterpret_cast<__half2*>(&dst[(size_t)s * HID + bn + 64 + i]);
            d1[0] = __floats2half2_rn((x1.x * co.x - x2.x * si.x) * qs,
                                      (x1.y * co.y - x2.y * si.y) * qs);
            d1[1] = __floats2half2_rn((x1.z * co.z - x2.z * si.z) * qs,
                                      (x1.w * co.w - x2.w * si.w) * qs);
            d2[0] = __floats2half2_rn((x2.x * co.x + x1.x * si.x) * qs,
                                      (x2.y * co.y + x1.y * si.y) * qs);
            d2[1] = __floats2half2_rn((x2.z * co.z + x1.z * si.z) * qs,
                                      (x2.w * co.w + x1.w * si.w) * qs);
        }
        return;
    }

#pragma unroll
    for (int im = 0; im < 2; im++) {
#pragma unroll
        for (int jn = 0; jn < 8; jn++) {
            int r = bm + wm * 32 + im * 16 + g;
            int col = bn + wn * 64 + jn * 8 + 2 * t;
            if (Ch) {
                *reinterpret_cast<__half2*>(&Ch[(size_t)r * N + col]) =
                    __floats2half2_rn(c[im][jn][0], c[im][jn][1]);
                *reinterpret_cast<__half2*>(&Ch[(size_t)(r + 8) * N + col]) =
                    __floats2half2_rn(c[im][jn][2], c[im][jn][3]);
            } else {
                *reinterpret_cast<float2*>(&Cf[(size_t)r * N + col]) =
                    make_float2(c[im][jn][0], c[im][jn][1]);
                *reinterpret_cast<float2*>(&Cf[(size_t)(r + 8) * N + col]) =
                    make_float2(c[im][jn][2], c[im][jn][3]);
            }
        }
    }
}

// ---------------- flash attention (causal), fp16 mma, running-max softmax -----
// (fixed-shift reverted for precision margin; single barrier per key-tile)
#define ABM 64
#define ABN 64
#define KVP 136                            // K tile pitch (halves)
#define KSTGH (ABN * KVP)                  // 8704 halves
#define VPITCH 72                          // V^T tile pitch (halves)
#define VSTGH (HD * VPITCH)                // 9216 halves
#define ATT_SMEM ((2 * KSTGH + 2 * VSTGH) * 2)  // 71680 B dynamic

__global__ void __launch_bounds__(128, 3) attn_kernel() {
    extern __shared__ __half kvdyn[];      // [K0, K1, V0, V1]

    int tid = threadIdx.x, lane = tid & 31, wid = tid >> 5;
    int g = lane >> 2, t = lane & 3;
    int qt = (int)(gridDim.x - 1 - blockIdx.x);   // heavy tiles first
    int h = blockIdx.y;
    int hoff = h * HD;
    int qrow = qt * ABM + wid * 16;
    int row0 = qrow + g, row1 = row0 + 8;

    uint32_t dynb = (uint32_t)__cvta_generic_to_shared(kvdyn);

    // ldmatrix lane address components
    int lrow = lane & 7, lm = lane >> 3;
    int kroff = ((((lm >> 1) * 8 + lrow) * KVP) + (lm & 1) * 8) * 2;     // bytes
    int vroff = ((((lm >> 1) * 8 + lrow) * VPITCH) + (lm & 1) * 8) * 2;  // bytes

    // Q fragments (pre-scaled by QSC): 8 k16-steps over HD=128
    uint32_t qf[8][4];
#pragma unroll
    for (int s = 0; s < 8; s++) {
        int cb = hoff + s * 16 + 2 * t;
        qf[s][0] = *reinterpret_cast<const uint32_t*>(&g_Qh[(size_t)row0 * HID + cb]);
        qf[s][1] = *reinterpret_cast<const uint32_t*>(&g_Qh[(size_t)row1 * HID + cb]);
        qf[s][2] = *reinterpret_cast<const uint32_t*>(&g_Qh[(size_t)row0 * HID + cb + 8]);
        qf[s][3] = *reinterpret_cast<const uint32_t*>(&g_Qh[(size_t)row1 * HID + cb + 8]);
    }

    float of[16][4];
#pragma unroll
    for (int j = 0; j < 16; j++) { of[j][0] = 0.f; of[j][1] = 0.f; of[j][2] = 0.f; of[j][3] = 0.f; }
    float m0 = -1e30f, m1 = -1e30f, l0 = 0.f, l1 = 0.f;   // l: per-lane partials

    auto loadKV = [&](int b, int kt) {
        const __half* Kg = g_Kh + (size_t)(kt * ABN) * HID + hoff;
        const __half* Vg = g_Vt + (size_t)hoff * SEQ + kt * ABN;
        uint32_t kb = dynb + (uint32_t)(b * KSTGH) * 2;
        uint32_t vb = dynb + (uint32_t)(2 * KSTGH + b * VSTGH) * 2;
#pragma unroll
        for (int j = 0; j < 8; j++) {       // K: 64 rows x 16 chunks = 1024
            int cidx = tid + 128 * j;
            int rr = cidx >> 4, c = cidx & 15;
            cpasync16(kb + (uint32_t)(rr * KVP + c * 8) * 2, Kg + (size_t)rr * HID + c * 8);
        }
#pragma unroll
        for (int j = 0; j < 8; j++) {       // V^T: 128 rows x 8 chunks = 1024
            int cidx = tid + 128 * j;
            int rr = cidx >> 3, c = cidx & 7;
            cpasync16(vb + (uint32_t)(rr * VPITCH + c * 8) * 2, Vg + (size_t)rr * SEQ + c * 8);
        }
    };

    int ktmax = qt;                         // tiles 0..qt; only kt==qt needs masking
    loadKV(0, 0);
    cpcommit();
    int buf = 0;

    for (int kt = 0; kt <= ktmax; kt++) {
        // single barrier: wait for tile kt, barrier, then prefetch kt+1.
        // Passing the barrier proves all warps finished compute kt-1, so
        // overwriting buf^1 is safe.
        asm volatile("cp.async.wait_group 0;" ::: "memory");
        __syncthreads();
        if (kt < ktmax) {
            loadKV(buf ^ 1, kt + 1);
            cpcommit();
        }

        uint32_t kbU = dynb + (uint32_t)(buf * KSTGH) * 2;
        uint32_t vbU = dynb + (uint32_t)(2 * KSTGH + buf * VSTGH) * 2;

        // scores (already log2-scaled via Q): Q (64x128) @ K^T (128x64)
        float sf[8][4];
#pragma unroll
        for (int j = 0; j < 8; j++) { sf[j][0] = 0.f; sf[j][1] = 0.f; sf[j][2] = 0.f; sf[j][3] = 0.f; }
#pragma unroll
        for (int s = 0; s < 8; s++) {
#pragma unroll
            for (int jj = 0; jj < 8; jj += 2) {
                uint32_t addr = kbU + (uint32_t)(jj * 8 * KVP * 2 + kroff + s * 32);
                uint32_t b0, b1, b2, b3;
                ldsm4(b0, b1, b2, b3, addr);
                mma_f16(sf[jj],     qf[s], b0, b1);
                mma_f16(sf[jj + 1], qf[s], b2, b3);
            }
        }

        // causal mask: only the diagonal tile needs it
        if (kt == qt) {
#pragma unroll
            for (int j = 0; j < 8; j++) {
                int cg = kt * ABN + j * 8 + 2 * t;
                if (cg     > row0) sf[j][0] = -1e30f;
                if (cg + 1 > row0) sf[j][1] = -1e30f;
                if (cg     > row1) sf[j][2] = -1e30f;
                if (cg + 1 > row1) sf[j][3] = -1e30f;
            }
        }

        // row max
        float mx0 = -1e30f, mx1 = -1e30f;
#pragma unroll
        for (int j = 0; j < 8; j++) {
            mx0 = fmaxf(mx0, fmaxf(sf[j][0], sf[j][1]));
            mx1 = fmaxf(mx1, fmaxf(sf[j][2], sf[j][3]));
        }
        mx0 = fmaxf(mx0, __shfl_xor_sync(0xffffffffu, mx0, 1));
        mx0 = fmaxf(mx0, __shfl_xor_sync(0xffffffffu, mx0, 2));
        mx1 = fmaxf(mx1, __shfl_xor_sync(0xffffffffu, mx1, 1));
        mx1 = fmaxf(mx1, __shfl_xor_sync(0xffffffffu, mx1, 2));

        float mn0 = fmaxf(m0, mx0), mn1 = fmaxf(m1, mx1);
        float al0 = exp2f(m0 - mn0), al1 = exp2f(m1 - mn1);

        // p = 2^(s - m) in packed half2; packed result is directly the PV A-frag.
        uint32_t p01[8], p23[8];
        float rs0 = 0.f, rs1 = 0.f;
#pragma unroll
        for (int j = 0; j < 8; j++) {
            uint32_t a01 = h2u(__floats2half2_rn(sf[j][0] - mn0, sf[j][1] - mn0));
            uint32_t a23 = h2u(__floats2half2_rn(sf[j][2] - mn1, sf[j][3] - mn1));
            uint32_t e01 = ex2_h2(a01);
            uint32_t e23 = ex2_h2(a23);
            p01[j] = e01; p23[j] = e23;
            float2 f01 = __half22float2(*reinterpret_cast<__half2*>(&e01));
            float2 f23 = __half22float2(*reinterpret_cast<__half2*>(&e23));
            rs0 += f01.x + f01.y;
            rs1 += f23.x + f23.y;
        }
        l0 = l0 * al0 + rs0;
        l1 = l1 * al1 + rs1;
        m0 = mn0; m1 = mn1;
#pragma unroll
        for (int j = 0; j < 16; j++) {
            of[j][0] *= al0; of[j][1] *= al0; of[j][2] *= al1; of[j][3] *= al1;
        }

        // PV: P (64x64) @ V (64x128); A from registers, B via ldmatrix.x4 on V^T
#pragma unroll
        for (int kb4 = 0; kb4 < 4; kb4++) {
            uint32_t a[4];
            a[0] = p01[2 * kb4];
            a[1] = p23[2 * kb4];
            a[2] = p01[2 * kb4 + 1];
            a[3] = p23[2 * kb4 + 1];
#pragma unroll
            for (int jj = 0; jj < 16; jj += 2) {
                uint32_t addr = vbU + (uint32_t)(jj * 8 * VPITCH * 2 + vroff + kb4 * 32);
                uint32_t b0, b1, b2, b3;
                ldsm4(b0, b1, b2, b3, addr);
                mma_f16(of[jj],     a, b0, b1);
                mma_f16(of[jj + 1], a, b2, b3);
            }
        }
        buf ^= 1;
    }

    // final per-lane l reduction
    l0 += __shfl_xor_sync(0xffffffffu, l0, 1);
    l0 += __shfl_xor_sync(0xffffffffu, l0, 2);
    l1 += __shfl_xor_sync(0xffffffffu, l1, 1);
    l1 += __shfl_xor_sync(0xffffffffu, l1, 2);

    float inv0 = 1.f / l0, inv1 = 1.f / l1;
#pragma unroll
    for (int j = 0; j < 16; j++) {
        int col = hoff + j * 8 + 2 * t;
        *reinterpret_cast<__half2*>(&g_ctxh[(size_t)row0 * HID + col]) =
            __floats2half2_rn(of[j][0] * inv0, of[j][1] * inv0);
        *reinterpret_cast<__half2*>(&g_ctxh[(size_t)row1 * HID + col]) =
            __floats2half2_rn(of[j][2] * inv1, of[j][3] * inv1);
    }
}

// ---------------- launch ----------------
extern "C" void kernel_launch(void* const* d_in, const int* in_sizes, int n_in,
                              void* d_out, int out_size) {
    const float* X  = (const float*)d_in[0];
    const float* Wq = (const float*)d_in[1];
    const float* Wk = (const float*)d_in[2];
    const float* Wv = (const float*)d_in[3];
    const float* Wo = (const float*)d_in[4];
    float* out = (float*)d_out;

    static int inited = 0;
    if (!inited) {
        cudaFuncSetAttribute(gemm_tn, cudaFuncAttributeMaxDynamicSharedMemorySize, GEMM_SMEM);
        cudaFuncSetAttribute(attn_kernel, cudaFuncAttributeMaxDynamicSharedMemorySize, ATT_SMEM);
        inited = 1;
    }

    tohalf_all<<<(NTOT + 1023) / 1024, 256>>>(X, Wq, Wk, Wv, Wo);
    rope_table<<<(SEQ * 64) / 256, 256>>>();

    // fused Q (pre-scaled), K (rope epilogue) and V^T in one launch
    dim3 gqkv(16, 32, 3);
    gemm_tn<<<gqkv, 256, GEMM_SMEM>>>(0, nullptr);

    attn_kernel<<<dim3(SEQ / ABM, NHEADS), 128, ATT_SMEM>>>();

    dim3 go(HID / GBN, SEQ / GBM, 1);       // output projection
    gemm_tn<<<go, 256, GEMM_SMEM>>>(2, out);
}

// round 17
// speedup vs baseline: 1.0172x; 1.0172x over previous
#include <cuda_runtime.h>
#include <cuda_fp16.h>
#include <cstdint>

#define SEQ 4096
#define HID 2048
#define NHEADS 16
#define HD 128

// Q pre-scale: (1/sqrt(128)) * log2(e)  -> softmax runs in exp2 domain
#define QSC 0.12751291181090523f

// ---------------- scratch (static device arrays; no allocation) ----------------
static __device__ __half g_Xh[SEQ * HID];
static __device__ __half g_Wqh[HID * HID];
static __device__ __half g_Wkh[HID * HID];
static __device__ __half g_Wvh[HID * HID];
static __device__ __half g_Woh[HID * HID];
static __device__ __half g_Qh[SEQ * HID];
static __device__ __half g_Kh[SEQ * HID];
static __device__ __half g_Vt[HID * SEQ];    // V TRANSPOSED: [dim][seq]
static __device__ __half g_ctxh[SEQ * HID];
static __device__ float  g_cos[SEQ * 64];
static __device__ float  g_sin[SEQ * 64];

// ---------------- helpers ----------------
__device__ __forceinline__ void mma_f16(float* c, const uint32_t* a, uint32_t b0, uint32_t b1) {
    asm volatile(
        "mma.sync.aligned.m16n8k16.row.col.f32.f16.f16.f32 "
        "{%0,%1,%2,%3}, {%4,%5,%6,%7}, {%8,%9}, {%0,%1,%2,%3};"
        : "+f"(c[0]), "+f"(c[1]), "+f"(c[2]), "+f"(c[3])
        : "r"(a[0]), "r"(a[1]), "r"(a[2]), "r"(a[3]), "r"(b0), "r"(b1));
}

__device__ __forceinline__ void ldsm4(uint32_t& r0, uint32_t& r1, uint32_t& r2, uint32_t& r3,
                                      uint32_t addr) {
    asm volatile("ldmatrix.sync.aligned.m8n8.x4.shared.b16 {%0,%1,%2,%3}, [%4];"
                 : "=r"(r0), "=r"(r1), "=r"(r2), "=r"(r3) : "r"(addr));
}

__device__ __forceinline__ void cpasync16(uint32_t dst, const void* src) {
    asm volatile("cp.async.cg.shared.global [%0], [%1], 16;" :: "r"(dst), "l"(src));
}
__device__ __forceinline__ void cpcommit() { asm volatile("cp.async.commit_group;"); }

__device__ __forceinline__ uint32_t h2u(__half2 h) {
    return *reinterpret_cast<uint32_t*>(&h);
}
__device__ __forceinline__ uint32_t ex2_h2(uint32_t x) {
    uint32_t r;
    asm("ex2.approx.f16x2 %0, %1;" : "=r"(r) : "r"(x));
    return r;
}

// ---------------- prep: fp32 -> fp16, 4 float4s per thread (MLP) --------------
#define NX (SEQ * HID / 4)
#define NW (HID * HID / 4)
#define NTOT (NX + 4 * NW)
__global__ void tohalf_all(const float* __restrict__ X,  const float* __restrict__ Wq,
                           const float* __restrict__ Wk, const float* __restrict__ Wv,
                           const float* __restrict__ Wo) {
    int base = blockIdx.x * (blockDim.x * 4) + threadIdx.x;
#pragma unroll
    for (int u = 0; u < 4; u++) {
        int i = base + u * blockDim.x;
        if (i >= NTOT) return;
        const float* src; __half* dst; int off;
        if (i < NX)               { src = X;  dst = g_Xh;  off = i; }
        else if (i < NX + NW)     { src = Wq; dst = g_Wqh; off = i - NX; }
        else if (i < NX + 2 * NW) { src = Wk; dst = g_Wkh; off = i - NX - NW; }
        else if (i < NX + 3 * NW) { src = Wv; dst = g_Wvh; off = i - NX - 2 * NW; }
        else                      { src = Wo; dst = g_Woh; off = i - NX - 3 * NW; }
        float4 v = reinterpret_cast<const float4*>(src)[off];
        __half2* p = reinterpret_cast<__half2*>(&dst[4 * off]);
        p[0] = __floats2half2_rn(v.x, v.y);
        p[1] = __floats2half2_rn(v.z, v.w);
    }
}

// ---------------- RoPE tables ----------------
__global__ void rope_table() {
    int idx = blockIdx.x * blockDim.x + threadIdx.x;
    if (idx >= SEQ * 64) return;
    int s = idx >> 6, j = idx & 63;
    double invf = exp(-(double)j * (9.210340371976184 / 64.0));  // 10000^(-j/64)
    float freq = (float)s * (float)invf;                          // fp32, like the ref
    g_cos[idx] = (float)cos((double)freq);
    g_sin[idx] = (float)sin((double)freq);
}

// ---------------- GEMM: C[M,N] = A[M,K] @ B[N,K]^T, fp16 mma, GBK=64, 3-stage --
// Single barrier per k-iteration (kept from R16: measured neutral-to-positive).
#define GBM 128
#define GBN 128
#define GBK 64
#define GST 3
#define APITCH 72                          // halves
#define AHALFS (GBM * APITCH)              // 9216
#define STGH (2 * AHALFS)                  // 18432 halves = 36864 B
#define GEMM_SMEM (GST * STGH * 2)         // 110592 B  (2 CTAs/SM)
#define CPITCH 132                         // fp32 epilogue staging pitch

__global__ void __launch_bounds__(256, 2) gemm_tn(int mode, float* __restrict__ extC) {
    extern __shared__ __half sm[];
    const __half* A; const __half* B;
    float* Cf = nullptr; __half* Ch = nullptr;
    int N;
    const int K = HID;
    int z = (int)blockIdx.z;
    int bm, bn;
    if (mode == 0) {
        if (z == 0)      { A = g_Xh;  B = g_Wqh; N = HID; }
        else if (z == 1) { A = g_Xh;  B = g_Wkh; N = HID; }
        else             { A = g_Wvh; B = g_Xh;  N = SEQ; Ch = g_Vt; }
        if (z == 2) { bm = blockIdx.x * GBM; bn = blockIdx.y * GBN; }   // 16 x 32
        else        { bm = blockIdx.y * GBM; bn = blockIdx.x * GBN; }   // 32 x 16
    } else {
        A = g_ctxh; B = g_Woh; N = HID; Cf = extC;
        bm = blockIdx.y * GBM; bn = blockIdx.x * GBN;
    }

    int tid = threadIdx.x;
    int lane = tid & 31, wid = tid >> 5;
    int wm = wid & 3, wn = wid >> 2;

    float c[2][8][4];
#pragma unroll
    for (int im = 0; im < 2; im++)
#pragma unroll
        for (int jn = 0; jn < 8; jn++)
#pragma unroll
            for (int q = 0; q < 4; q++) c[im][jn][q] = 0.f;

    const __half* Abase = A + (size_t)bm * K;
    const __half* Bbase = B + (size_t)bn * K;

    uint32_t smb = (uint32_t)__cvta_generic_to_shared(sm);

    int lr = tid >> 3, lc8 = tid & 7;

    // ldmatrix lane address components
    int lrow = lane & 7;
    int arow = ((lane >> 3) & 1) * 8 + lrow;   // A: m0/m1 = row-halves, m2/m3 = k-hi
    int acol = (lane >> 4) * 8;
    int brow = (lane >> 4) * 8 + lrow;         // B: m0/m1 = k-halves of jj, m2/m3 = jj+1
    int bcol = ((lane >> 3) & 1) * 8;

    auto load_tile = [&](int s, int kt) {
        int koff = kt * GBK + lc8 * 8;
        uint32_t sa = smb + (uint32_t)(s * STGH) * 2;
        uint32_t sb = sa + AHALFS * 2;
        uint32_t doff = (uint32_t)(lr * APITCH + lc8 * 8) * 2;
#pragma unroll
        for (int i = 0; i < 4; i++) {
            int r = lr + 32 * i;
            cpasync16(sa + doff + (uint32_t)(32 * i * APITCH) * 2, Abase + (size_t)r * K + koff);
            cpasync16(sb + doff + (uint32_t)(32 * i * APITCH) * 2, Bbase + (size_t)r * K + koff);
        }
    };

    const int NT = K / GBK;  // 32
    load_tile(0, 0); cpcommit();
    load_tile(1, 1); cpcommit();

    int g = lane >> 2, t = lane & 3;
    int stg = 0;

    for (int kt = 0; kt < NT; kt++) {
        if (kt + 2 < NT) {
            asm volatile("cp.async.wait_group 1;" ::: "memory");
            __syncthreads();
            int ns = stg + 2; if (ns >= GST) ns -= GST;
            load_tile(ns, kt + 2);
            cpcommit();
        } else {
            asm volatile("cp.async.wait_group 0;" ::: "memory");
            __syncthreads();
        }

        uint32_t saU = smb + (uint32_t)(stg * STGH) * 2;
        uint32_t sbU = saU + AHALFS * 2;
#pragma unroll
        for (int ks = 0; ks < 4; ks++) {
            int k0 = ks * 16;
            uint32_t a[2][4], b[8][2];
#pragma unroll
            for (int im = 0; im < 2; im++) {
                uint32_t addr = saU +
                    (uint32_t)(((wm * 32 + im * 16 + arow) * APITCH + k0 + acol) * 2);
                ldsm4(a[im][0], a[im][1], a[im][2], a[im][3], addr);
            }
#pragma unroll
            for (int jj = 0; jj < 8; jj += 2) {
                uint32_t addr = sbU +
                    (uint32_t)(((wn * 64 + jj * 8 + brow) * APITCH + k0 + bcol) * 2);
                ldsm4(b[jj][0], b[jj][1], b[jj + 1][0], b[jj + 1][1], addr);
            }
#pragma unroll
            for (int im = 0; im < 2; im++)
#pragma unroll
                for (int jn = 0; jn < 8; jn++)
                    mma_f16(c[im][jn], a[im], b[jn][0], b[jn][1]);
        }
        if (++stg == GST) stg = 0;
    }

    if (mode == 0 && z < 2) {
        // ---- fused RoPE epilogue: stage fp32 C in smem, pair (i, i+64), write half
        __syncthreads();                       // mainloop smem reads done
        float* cs = reinterpret_cast<float*>(sm);
#pragma unroll
        for (int im = 0; im < 2; im++)
#pragma unroll
            for (int jn = 0; jn < 8; jn++) {
                int r = wm * 32 + im * 16 + g;
                int lc = wn * 64 + jn * 8 + 2 * t;
                cs[r * CPITCH + lc]           = c[im][jn][0];
                cs[r * CPITCH + lc + 1]       = c[im][jn][1];
                cs[(r + 8) * CPITCH + lc]     = c[im][jn][2];
                cs[(r + 8) * CPITCH + lc + 1] = c[im][jn][3];
            }
        __syncthreads();
        __half* dst = (z == 0) ? g_Qh : g_Kh;
        float qs = (z == 0) ? QSC : 1.0f;      // Q carries softmax scale (log2 domain)
        int r = tid >> 1;
        int i0 = (tid & 1) * 32;
        int s = bm + r;
        const float* crow = cs + r * CPITCH;
#pragma unroll
        for (int ii = 0; ii < 32; ii += 4) {
            int i = i0 + ii;
            float4 x1 = *reinterpret_cast<const float4*>(&crow[i]);
            float4 x2 = *reinterpret_cast<const float4*>(&crow[i + 64]);
            float4 co = *reinterpret_cast<const float4*>(&g_cos[s * 64 + i]);
            float4 si = *reinterpret_cast<const float4*>(&g_sin[s * 64 + i]);
            __half2* d1 = reinterpret_cast<__half2*>(&dst[(size_t)s * HID + bn + i]);
            __half2* d2 = reinterpret_cast<__half2*>(&dst[(size_t)s * HID + bn + 64 + i]);
            d1[0] = __floats2half2_rn((x1.x * co.x - x2.x * si.x) * qs,
                                      (x1.y * co.y - x2.y * si.y) * qs);
            d1[1] = __floats2half2_rn((x1.z * co.z - x2.z * si.z) * qs,
                                      (x1.w * co.w - x2.w * si.w) * qs);
            d2[0] = __floats2half2_rn((x2.x * co.x + x1.x * si.x) * qs,
                                      (x2.y * co.y + x1.y * si.y) * qs);
            d2[1] = __floats2half2_rn((x2.z * co.z + x1.z * si.z) * qs,
                                      (x2.w * co.w + x1.w * si.w) * qs);
        }
        return;
    }

#pragma unroll
    for (int im = 0; im < 2; im++) {
#pragma unroll
        for (int jn = 0; jn < 8; jn++) {
            int r = bm + wm * 32 + im * 16 + g;
            int col = bn + wn * 64 + jn * 8 + 2 * t;
            if (Ch) {
                *reinterpret_cast<__half2*>(&Ch[(size_t)r * N + col]) =
                    __floats2half2_rn(c[im][jn][0], c[im][jn][1]);
                *reinterpret_cast<__half2*>(&Ch[(size_t)(r + 8) * N + col]) =
                    __floats2half2_rn(c[im][jn][2], c[im][jn][3]);
            } else {
                *reinterpret_cast<float2*>(&Cf[(size_t)r * N + col]) =
                    make_float2(c[im][jn][0], c[im][jn][1]);
                *reinterpret_cast<float2*>(&Cf[(size_t)(r + 8) * N + col]) =
                    make_float2(c[im][jn][2], c[im][jn][3]);
            }
        }
    }
}

// ---------------- flash attention (causal), fp16 mma, running-max softmax -----
// Pipeline restored to the round-14 proven two-barrier form (prefetch issued
// BEFORE wait_group 1) — the R16 single-barrier variant cost 24 us.
#define ABM 64
#define ABN 64
#define KVP 136                            // K tile pitch (halves)
#define KSTGH (ABN * KVP)                  // 8704 halves
#define VPITCH 72                          // V^T tile pitch (halves)
#define VSTGH (HD * VPITCH)                // 9216 halves
#define ATT_SMEM ((2 * KSTGH + 2 * VSTGH) * 2)  // 71680 B dynamic

__global__ void __launch_bounds__(128, 3) attn_kernel() {
    extern __shared__ __half kvdyn[];      // [K0, K1, V0, V1]

    int tid = threadIdx.x, lane = tid & 31, wid = tid >> 5;
    int g = lane >> 2, t = lane & 3;
    int qt = (int)(gridDim.x - 1 - blockIdx.x);   // heavy tiles first
    int h = blockIdx.y;
    int hoff = h * HD;
    int qrow = qt * ABM + wid * 16;
    int row0 = qrow + g, row1 = row0 + 8;

    uint32_t dynb = (uint32_t)__cvta_generic_to_shared(kvdyn);

    // ldmatrix lane address components
    int lrow = lane & 7, lm = lane >> 3;
    int kroff = ((((lm >> 1) * 8 + lrow) * KVP) + (lm & 1) * 8) * 2;     // bytes
    int vroff = ((((lm >> 1) * 8 + lrow) * VPITCH) + (lm & 1) * 8) * 2;  // bytes

    // Q fragments (pre-scaled by QSC): 8 k16-steps over HD=128
    uint32_t qf[8][4];
#pragma unroll
    for (int s = 0; s < 8; s++) {
        int cb = hoff + s * 16 + 2 * t;
        qf[s][0] = *reinterpret_cast<const uint32_t*>(&g_Qh[(size_t)row0 * HID + cb]);
        qf[s][1] = *reinterpret_cast<const uint32_t*>(&g_Qh[(size_t)row1 * HID + cb]);
        qf[s][2] = *reinterpret_cast<const uint32_t*>(&g_Qh[(size_t)row0 * HID + cb + 8]);
        qf[s][3] = *reinterpret_cast<const uint32_t*>(&g_Qh[(size_t)row1 * HID + cb + 8]);
    }

    float of[16][4];
#pragma unroll
    for (int j = 0; j < 16; j++) { of[j][0] = 0.f; of[j][1] = 0.f; of[j][2] = 0.f; of[j][3] = 0.f; }
    float m0 = -1e30f, m1 = -1e30f, l0 = 0.f, l1 = 0.f;   // l: per-lane partials

    auto loadKV = [&](int b, int kt) {
        const __half* Kg = g_Kh + (size_t)(kt * ABN) * HID + hoff;
        const __half* Vg = g_Vt + (size_t)hoff * SEQ + kt * ABN;
        uint32_t kb = dynb + (uint32_t)(b * KSTGH) * 2;
        uint32_t vb = dynb + (uint32_t)(2 * KSTGH + b * VSTGH) * 2;
#pragma unroll
        for (int j = 0; j < 8; j++) {       // K: 64 rows x 16 chunks = 1024
            int cidx = tid + 128 * j;
            int rr = cidx >> 4, c = cidx & 15;
            cpasync16(kb + (uint32_t)(rr * KVP + c * 8) * 2, Kg + (size_t)rr * HID + c * 8);
        }
#pragma unroll
        for (int j = 0; j < 8; j++) {       // V^T: 128 rows x 8 chunks = 1024
            int cidx = tid + 128 * j;
            int rr = cidx >> 3, c = cidx & 7;
            cpasync16(vb + (uint32_t)(rr * VPITCH + c * 8) * 2, Vg + (size_t)rr * SEQ + c * 8);
        }
    };

    int ktmax = qt;                         // tiles 0..qt; only kt==qt needs masking
    loadKV(0, 0);
    cpcommit();
    int buf = 0;

    for (int kt = 0; kt <= ktmax; kt++) {
        if (kt < ktmax) {
            if (kt > 0) __syncthreads();
            loadKV(buf ^ 1, kt + 1);
            cpcommit();
            asm volatile("cp.async.wait_group 1;" ::: "memory");
        } else {
            if (kt > 0) __syncthreads();
            asm volatile("cp.async.wait_group 0;" ::: "memory");
        }
        __syncthreads();

        uint32_t kbU = dynb + (uint32_t)(buf * KSTGH) * 2;
        uint32_t vbU = dynb + (uint32_t)(2 * KSTGH + buf * VSTGH) * 2;

        // scores (already log2-scaled via Q): Q (64x128) @ K^T (128x64)
        float sf[8][4];
#pragma unroll
        for (int j = 0; j < 8; j++) { sf[j][0] = 0.f; sf[j][1] = 0.f; sf[j][2] = 0.f; sf[j][3] = 0.f; }
#pragma unroll
        for (int s = 0; s < 8; s++) {
#pragma unroll
            for (int jj = 0; jj < 8; jj += 2) {
                uint32_t addr = kbU + (uint32_t)(jj * 8 * KVP * 2 + kroff + s * 32);
                uint32_t b0, b1, b2, b3;
                ldsm4(b0, b1, b2, b3, addr);
                mma_f16(sf[jj],     qf[s], b0, b1);
                mma_f16(sf[jj + 1], qf[s], b2, b3);
            }
        }

        // causal mask: only the diagonal tile needs it
        if (kt == qt) {
#pragma unroll
            for (int j = 0; j < 8; j++) {
                int cg = kt * ABN + j * 8 + 2 * t;
                if (cg     > row0) sf[j][0] = -1e30f;
                if (cg + 1 > row0) sf[j][1] = -1e30f;
                if (cg     > row1) sf[j][2] = -1e30f;
                if (cg + 1 > row1) sf[j][3] = -1e30f;
            }
        }

        // row max
        float mx0 = -1e30f, mx1 = -1e30f;
#pragma unroll
        for (int j = 0; j < 8; j++) {
            mx0 = fmaxf(mx0, fmaxf(sf[j][0], sf[j][1]));
            mx1 = fmaxf(mx1, fmaxf(sf[j][2], sf[j][3]));
        }
        mx0 = fmaxf(mx0, __shfl_xor_sync(0xffffffffu, mx0, 1));
        mx0 = fmaxf(mx0, __shfl_xor_sync(0xffffffffu, mx0, 2));
        mx1 = fmaxf(mx1, __shfl_xor_sync(0xffffffffu, mx1, 1));
        mx1 = fmaxf(mx1, __shfl_xor_sync(0xffffffffu, mx1, 2));

        float mn0 = fmaxf(m0, mx0), mn1 = fmaxf(m1, mx1);
        float al0 = exp2f(m0 - mn0), al1 = exp2f(m1 - mn1);

        // p = 2^(s - m) in packed half2; packed result is directly the PV A-frag.
        uint32_t p01[8], p23[8];
        float rs0 = 0.f, rs1 = 0.f;
#pragma unroll
        for (int j = 0; j < 8; j++) {
            uint32_t a01 = h2u(__floats2half2_rn(sf[j][0] - mn0, sf[j][1] - mn0));
            uint32_t a23 = h2u(__floats2half2_rn(sf[j][2] - mn1, sf[j][3] - mn1));
            uint32_t e01 = ex2_h2(a01);
            uint32_t e23 = ex2_h2(a23);
            p01[j] = e01; p23[j] = e23;
            float2 f01 = __half22float2(*reinterpret_cast<__half2*>(&e01));
            float2 f23 = __half22float2(*reinterpret_cast<__half2*>(&e23));
            rs0 += f01.x + f01.y;
            rs1 += f23.x + f23.y;
        }
        l0 = l0 * al0 + rs0;
        l1 = l1 * al1 + rs1;
        m0 = mn0; m1 = mn1;
#pragma unroll
        for (int j = 0; j < 16; j++) {
            of[j][0] *= al0; of[j][1] *= al0; of[j][2] *= al1; of[j][3] *= al1;
        }

        // PV: P (64x64) @ V (64x128); A from registers, B via ldmatrix.x4 on V^T
#pragma unroll
        for (int kb4 = 0; kb4 < 4; kb4++) {
            uint32_t a[4];
            a[0] = p01[2 * kb4];
            a[1] = p23[2 * kb4];
            a[2] = p01[2 * kb4 + 1];
            a[3] = p23[2 * kb4 + 1];
#pragma unroll
            for (int jj = 0; jj < 16; jj += 2) {
                uint32_t addr = vbU + (uint32_t)(jj * 8 * VPITCH * 2 + vroff + kb4 * 32);
                uint32_t b0, b1, b2, b3;
                ldsm4(b0, b1, b2, b3, addr);
                mma_f16(of[jj],     a, b0, b1);
                mma_f16(of[jj + 1], a, b2, b3);
            }
        }
        buf ^= 1;
    }

    // final per-lane l reduction
    l0 += __shfl_xor_sync(0xffffffffu, l0, 1);
    l0 += __shfl_xor_sync(0xffffffffu, l0, 2);
    l1 += __shfl_xor_sync(0xffffffffu, l1, 1);
    l1 += __shfl_xor_sync(0xffffffffu, l1, 2);

    float inv0 = 1.f / l0, inv1 = 1.f / l1;
#pragma unroll
    for (int j = 0; j < 16; j++) {
        int col = hoff + j * 8 + 2 * t;
        *reinterpret_cast<__half2*>(&g_ctxh[(size_t)row0 * HID + col]) =
            __floats2half2_rn(of[j][0] * inv0, of[j][1] * inv0);
        *reinterpret_cast<__half2*>(&g_ctxh[(size_t)row1 * HID + col]) =
            __floats2half2_rn(of[j][2] * inv1, of[j][3] * inv1);
    }
}

// ---------------- launch ----------------
extern "C" void kernel_launch(void* const* d_in, const int* in_sizes, int n_in,
                              void* d_out, int out_size) {
    const float* X  = (const float*)d_in[0];
    const float* Wq = (const float*)d_in[1];
    const float* Wk = (const float*)d_in[2];
    const float* Wv = (const float*)d_in[3];
    const float* Wo = (const float*)d_in[4];
    float* out = (float*)d_out;

    static int inited = 0;
    if (!inited) {
        cudaFuncSetAttribute(gemm_tn, cudaFuncAttributeMaxDynamicSharedMemorySize, GEMM_SMEM);
        cudaFuncSetAttribute(attn_kernel, cudaFuncAttributeMaxDynamicSharedMemorySize, ATT_SMEM);
        inited = 1;
    }

    tohalf_all<<<(NTOT + 1023) / 1024, 256>>>(X, Wq, Wk, Wv, Wo);
    rope_table<<<(SEQ * 64) / 256, 256>>>();

    // fused Q (pre-scaled), K (rope epilogue) and V^T in one launch
    dim3 gqkv(16, 32, 3);
    gemm_tn<<<gqkv, 256, GEMM_SMEM>>>(0, nullptr);

    attn_kernel<<<dim3(SEQ / ABM, NHEADS), 128, ATT_SMEM>>>();

    dim3 go(HID / GBN, SEQ / GBM, 1);       // output projection
    gemm_tn<<<go, 256, GEMM_SMEM>>>(2, out);
}